// round 16
// baseline (speedup 1.0000x reference)
#include <cuda_runtime.h>
#include <cuda_bf16.h>
#include <math_constants.h>

#define NB 8192
#define GRID 1024           // 1024 CTAs x 4 warps x 2 samples = 8192 samples
#define THREADS 128
#define DEPTH 6             // rolling-ring depth (R8 used 4; steady > burst)
#define FP_SCALE 32768.0    // 2^15 fixed point (deterministic integer accumulation)

__device__ unsigned long long g_acc;
__device__ unsigned int g_done;

// Packed fp32x2 ops (Blackwell FFMA2 path — PTX-only)
#define ADDX2(d, a, b)    asm("add.rn.f32x2 %0,%1,%2;"    : "=l"(d) : "l"(a), "l"(b))
#define FMAX2(d, a, b, c) asm("fma.rn.f32x2 %0,%1,%2,%3;" : "=l"(d) : "l"(a), "l"(b), "l"(c))
#define PACKX2(d, lo, hi) asm("mov.b64 %0,{%1,%2};"       : "=l"(d) : "f"(lo), "f"(hi))
#define UNPACKX2(lo, hi, d) asm("mov.b64 {%0,%1},%2;"     : "=f"(lo), "=f"(hi) : "l"(d))

// 128-bit load with 256B L2 refill granularity (proven lever on this shape)
__device__ __forceinline__ float4 ld4_pf(const float4* p) {
    float4 v;
    asm volatile("ld.global.nc.L2::256B.v4.f32 {%0,%1,%2,%3}, [%4];"
                 : "=f"(v.x), "=f"(v.y), "=f"(v.z), "=f"(v.w) : "l"(p));
    return v;
}

__global__ void __launch_bounds__(THREADS, 6)
loss_kernel(const float* __restrict__ x, float* __restrict__ out) {
    const int t = threadIdx.x;
    const int w = t >> 5;
    const int l = t & 31;
    const int warp_g = blockIdx.x * 4 + w;

    __shared__ float wloss[4];

    const unsigned long long C23 = 0x4040000040000000ULL; // (2.0f, 3.0f)
    const unsigned long long C49 = 0x4110000040800000ULL; // (4.0f, 9.0f)

    float acc_loss = 0.f;

    #pragma unroll
    for (int s = 0; s < 2; ++s) {
        const int b = warp_g + s * 4096;
        const float4* __restrict__ xp =
            reinterpret_cast<const float4*>(x) + (size_t)b * 1024 + l;

        // Packed accumulators (bit-zero == (0.f, 0.f))
        unsigned long long s0p = 0, Up = 0, Vp = 0, mp1 = 0, mp2 = 0;
        float sy = 0.f;
        float bv = -CUDART_INF_F;
        int   bi = 0x7fffffff;

        // DEPTH-deep steady rolling ring over 32 chunks
        float4 buf[DEPTH];
        #pragma unroll
        for (int i = 0; i < DEPTH; ++i) buf[i] = ld4_pf(&xp[i * 32]);

        #pragma unroll
        for (int c = 0; c < 32; ++c) {
            const float4 v = buf[c % DEPTH];

            // steady refill: one load issued per chunk consumed
            if (c < 32 - DEPTH)
                buf[c % DEPTH] = ld4_pf(&xp[(c + DEPTH) * 32]);

            const float X = v.x, Y = v.y, Z = v.z, W = v.w;
            unsigned long long p0, p1, lsp;
            PACKX2(p0, X, Y);
            PACKX2(p1, Z, W);
            ADDX2(lsp, p0, p1);                 // (X+Z, Y+W)
            ADDX2(s0p, s0p, lsp);               // running sum
            ADDX2(Up,  Up,  s0p);               // prefix of prefix -> c-moment
            ADDX2(Vp,  Vp,  Up);                // -> c^2-moment
            FMAX2(mp1, p1, C23, mp1);           // 2Z + 3W
            FMAX2(mp2, p1, C49, mp2);           // 4Z + 9W
            sy += Y;                            // Y coeff is 1 in both m1,m2

            const float m = fmaxf(fmaxf(X, Y), fmaxf(Z, W));
            if (m > bv) {                       // first-max: strict '>', c ascending
                bv = m;
                const int cc = (m == X) ? 0 : ((m == Y) ? 1 : ((m == Z) ? 2 : 3));
                bi = ((c * 32 + l) << 2) + cc;
            }
        }

        // ---- fold packed accumulators ----
        float s0lo, s0hi, Ulo, Uhi, Vlo, Vhi, m1lo, m1hi, m2lo, m2hi;
        UNPACKX2(s0lo, s0hi, s0p);
        UNPACKX2(Ulo, Uhi, Up);
        UNPACKX2(Vlo, Vhi, Vp);
        UNPACKX2(m1lo, m1hi, mp1);
        UNPACKX2(m2lo, m2hi, mp2);

        float s0 = s0lo + s0hi;
        const float cU = Ulo + Uhi;
        const float cV = Vlo + Vhi;
        // Sum c*ls = 32*s0 - U ;  Sum c^2*ls = 1024*s0 - 65*U + 2*V
        const float sc1 = fmaf(32.f, s0, -cU);
        const float sc2 = fmaf(1024.f, s0, fmaf(-65.f, cU, 2.f * cV));
        // j = 2c + jh
        const float jh = (float)(l >> 4);
        float sj  = fmaf(2.f, sc1, jh * s0);
        float sjj = fmaf(4.f, sc2, fmaf(4.f * jh, sc1, jh * s0)); // jh^2 == jh
        // k = k0 + cc  (k0 thread-constant)
        const float m1 = sy + m1lo + m1hi;
        const float m2 = sy + m2lo + m2hi;
        const float k0 = (float)((l & 15) << 2);
        float sk  = fmaf(k0, s0, m1);
        const float skk = fmaf(k0 * k0, s0, fmaf(2.f * k0, m1, m2));
        float sq = sjj + skk;

        // ---- warp-only reduction ----
        #pragma unroll
        for (int off = 16; off > 0; off >>= 1) {
            s0 += __shfl_down_sync(0xffffffffu, s0, off);
            sj += __shfl_down_sync(0xffffffffu, sj, off);
            sk += __shfl_down_sync(0xffffffffu, sk, off);
            sq += __shfl_down_sync(0xffffffffu, sq, off);
            const float ov = __shfl_down_sync(0xffffffffu, bv, off);
            const int   oi = __shfl_down_sync(0xffffffffu, bi, off);
            if (ov > bv || (ov == bv && oi < bi)) { bv = ov; bi = oi; }
        }

        if (l == 0) {
            const float mx = (float)(bi >> 6);
            const float my = (float)(bi & 63);
            acc_loss += (mx * mx + my * my) * s0
                      - 2.f * mx * sj
                      - 2.f * my * sk
                      + sq;
        }
    }

    if (l == 0) wloss[w] = acc_loss;
    __syncthreads();

    if (t == 0) {
        const double tot = (double)wloss[0] + (double)wloss[1]
                         + (double)wloss[2] + (double)wloss[3];
        const long long q = llrint(tot * FP_SCALE);
        atomicAdd(&g_acc, (unsigned long long)q);
        __threadfence();
        const unsigned int n = atomicAdd(&g_done, 1u);
        if (n == GRID - 1u) {
            const long long totq = (long long)atomicExch(&g_acc, 0ULL);
            g_done = 0;
            out[0] = (float)((double)totq / FP_SCALE);
        }
    }
}

extern "C" void kernel_launch(void* const* d_in, const int* in_sizes, int n_in,
                              void* d_out, int out_size) {
    const float* x = (const float*)d_in[0];
    float* out = (float*)d_out;
    loss_kernel<<<GRID, THREADS>>>(x, out);
}

// round 17
// speedup vs baseline: 1.0491x; 1.0491x over previous
#include <cuda_runtime.h>
#include <cuda_bf16.h>
#include <math_constants.h>

#define NB 8192
#define GRID 1024           // 1024 CTAs x 4 warps x 2 samples = 8192 samples
#define THREADS 128
#define FP_SCALE 32768.0    // 2^15 fixed point (deterministic integer accumulation)

__device__ unsigned long long g_acc;
__device__ unsigned int g_done;

// Packed fp32x2 ops (Blackwell FFMA2 path — PTX-only)
#define ADDX2(d, a, b)    asm("add.rn.f32x2 %0,%1,%2;"    : "=l"(d) : "l"(a), "l"(b))
#define FMAX2(d, a, b, c) asm("fma.rn.f32x2 %0,%1,%2,%3;" : "=l"(d) : "l"(a), "l"(b), "l"(c))
#define PACKX2(d, lo, hi) asm("mov.b64 %0,{%1,%2};"       : "=l"(d) : "f"(lo), "f"(hi))
#define UNPACKX2(lo, hi, d) asm("mov.b64 {%0,%1},%2;"     : "=f"(lo), "=f"(hi) : "l"(d))

// 128-bit load with 256B L2 refill granularity: the one measured bandwidth
// lever for this read-once stream (5.2 -> 5.56 TB/s on this shape).
__device__ __forceinline__ float4 ld4_pf(const float4* p) {
    float4 v;
    asm volatile("ld.global.nc.L2::256B.v4.f32 {%0,%1,%2,%3}, [%4];"
                 : "=f"(v.x), "=f"(v.y), "=f"(v.z), "=f"(v.w) : "l"(p));
    return v;
}

__global__ void __launch_bounds__(THREADS, 7)
loss_kernel(const float* __restrict__ x, float* __restrict__ out) {
    const int t = threadIdx.x;
    const int w = t >> 5;
    const int l = t & 31;
    const int warp_g = blockIdx.x * 4 + w;

    __shared__ float wloss[4];

    const unsigned long long C23 = 0x4040000040000000ULL; // (2.0f, 3.0f)
    const unsigned long long C49 = 0x4110000040800000ULL; // (4.0f, 9.0f)

    float acc_loss = 0.f;

    #pragma unroll
    for (int s = 0; s < 2; ++s) {
        const int b = warp_g + s * 4096;
        const float4* __restrict__ xp =
            reinterpret_cast<const float4*>(x) + (size_t)b * 1024 + l;

        // Packed accumulators (bit-zero == (0.f, 0.f))
        unsigned long long s0p = 0, Up = 0, Vp = 0, mp1 = 0, mp2 = 0;
        float sy = 0.f;
        float bv = -CUDART_INF_F;
        int   bi = 0x7fffffff;

        // 4-deep rolling prefetch over 32 chunks (8 groups of 4)
        float4 buf[4];
        #pragma unroll
        for (int i = 0; i < 4; ++i) buf[i] = ld4_pf(&xp[i * 32]);

        #pragma unroll
        for (int g = 0; g < 8; ++g) {
            float4 nbuf[4];
            if (g < 7) {
                #pragma unroll
                for (int i = 0; i < 4; ++i)
                    nbuf[i] = ld4_pf(&xp[(g + 1) * 128 + i * 32]);
            }
            #pragma unroll
            for (int i = 0; i < 4; ++i) {
                const int c = g * 4 + i;            // chunk index 0..31
                const float X = buf[i].x, Y = buf[i].y, Z = buf[i].z, W = buf[i].w;
                unsigned long long p0, p1, lsp;
                PACKX2(p0, X, Y);
                PACKX2(p1, Z, W);
                ADDX2(lsp, p0, p1);                 // (X+Z, Y+W)
                ADDX2(s0p, s0p, lsp);               // running sum
                ADDX2(Up,  Up,  s0p);               // prefix of prefix -> c-moment
                ADDX2(Vp,  Vp,  Up);                // -> c^2-moment
                FMAX2(mp1, p1, C23, mp1);           // 2Z + 3W
                FMAX2(mp2, p1, C49, mp2);           // 4Z + 9W
                sy += Y;                            // Y coeff is 1 in both m1,m2

                const float m = fmaxf(fmaxf(X, Y), fmaxf(Z, W));
                if (m > bv) {                       // first-max: strict '>', c ascending
                    bv = m;
                    const int cc = (m == X) ? 0 : ((m == Y) ? 1 : ((m == Z) ? 2 : 3));
                    bi = ((c * 32 + l) << 2) + cc;
                }
            }
            #pragma unroll
            for (int i = 0; i < 4; ++i) buf[i] = nbuf[i];
        }

        // ---- fold packed accumulators ----
        float s0lo, s0hi, Ulo, Uhi, Vlo, Vhi, m1lo, m1hi, m2lo, m2hi;
        UNPACKX2(s0lo, s0hi, s0p);
        UNPACKX2(Ulo, Uhi, Up);
        UNPACKX2(Vlo, Vhi, Vp);
        UNPACKX2(m1lo, m1hi, mp1);
        UNPACKX2(m2lo, m2hi, mp2);

        float s0 = s0lo + s0hi;
        const float cU = Ulo + Uhi;
        const float cV = Vlo + Vhi;
        // Sum c*ls = 32*s0 - U ;  Sum c^2*ls = 1024*s0 - 65*U + 2*V
        const float sc1 = fmaf(32.f, s0, -cU);
        const float sc2 = fmaf(1024.f, s0, fmaf(-65.f, cU, 2.f * cV));
        // j = 2c + jh
        const float jh = (float)(l >> 4);
        float sj  = fmaf(2.f, sc1, jh * s0);
        float sjj = fmaf(4.f, sc2, fmaf(4.f * jh, sc1, jh * s0)); // jh^2 == jh
        // k = k0 + cc  (k0 thread-constant)
        const float m1 = sy + m1lo + m1hi;
        const float m2 = sy + m2lo + m2hi;
        const float k0 = (float)((l & 15) << 2);
        float sk  = fmaf(k0, s0, m1);
        const float skk = fmaf(k0 * k0, s0, fmaf(2.f * k0, m1, m2));
        float sq = sjj + skk;

        // ---- warp-only reduction ----
        #pragma unroll
        for (int off = 16; off > 0; off >>= 1) {
            s0 += __shfl_down_sync(0xffffffffu, s0, off);
            sj += __shfl_down_sync(0xffffffffu, sj, off);
            sk += __shfl_down_sync(0xffffffffu, sk, off);
            sq += __shfl_down_sync(0xffffffffu, sq, off);
            const float ov = __shfl_down_sync(0xffffffffu, bv, off);
            const int   oi = __shfl_down_sync(0xffffffffu, bi, off);
            if (ov > bv || (ov == bv && oi < bi)) { bv = ov; bi = oi; }
        }

        if (l == 0) {
            const float mx = (float)(bi >> 6);
            const float my = (float)(bi & 63);
            acc_loss += (mx * mx + my * my) * s0
                      - 2.f * mx * sj
                      - 2.f * my * sk
                      + sq;
        }
    }

    if (l == 0) wloss[w] = acc_loss;
    __syncthreads();

    if (t == 0) {
        const double tot = (double)wloss[0] + (double)wloss[1]
                         + (double)wloss[2] + (double)wloss[3];
        const long long q = llrint(tot * FP_SCALE);
        atomicAdd(&g_acc, (unsigned long long)q);
        __threadfence();
        const unsigned int n = atomicAdd(&g_done, 1u);
        if (n == GRID - 1u) {
            const long long totq = (long long)atomicExch(&g_acc, 0ULL);
            g_done = 0;
            out[0] = (float)((double)totq / FP_SCALE);
        }
    }
}

extern "C" void kernel_launch(void* const* d_in, const int* in_sizes, int n_in,
                              void* d_out, int out_size) {
    const float* x = (const float*)d_in[0];
    float* out = (float*)d_out;
    loss_kernel<<<GRID, THREADS>>>(x, out);
}